// round 1
// baseline (speedup 1.0000x reference)
#include <cuda_runtime.h>

// WideAndDeepModel fused kernel, sm_103a.
// Strategy: 128 persistent CTAs x 256 threads. All weights (BN-folded) live in
// SMEM; each CTA processes 4 tiles of 32 rows. Per-thread register fragments,
// packed fp32 FMA via fma.rn.f32x2 (sm_100+ only; 2x the FFMA rate).

#define TILE    32
#define THREADS 256
#define BATCH   16384
#define NTILES  (BATCH / TILE)   // 512
#define GRID    128
#define TPC     (NTILES / GRID)  // 4

#define XS  168   // x row stride (164 + pad)
#define H1S 132   // h1 row stride (128 + pad)
#define H2S 68    // h2 row stride (64 + pad)
#define H3S 36    // h3 row stride (32 + pad)

// ---- packed f32x2 helpers ----
__device__ __forceinline__ unsigned long long pk2(float a, float b) {
    unsigned long long r;
    asm("mov.b64 %0, {%1, %2};" : "=l"(r) : "f"(a), "f"(b));
    return r;
}
__device__ __forceinline__ void upk2(unsigned long long v, float& a, float& b) {
    asm("mov.b64 {%0, %1}, %2;" : "=f"(a), "=f"(b) : "l"(v));
}
__device__ __forceinline__ void ffma2(unsigned long long& d, unsigned long long a,
                                      unsigned long long b) {
    asm("fma.rn.f32x2 %0, %1, %2, %0;" : "+l"(d) : "l"(a), "l"(b));
}

extern __shared__ float sm[];

__global__ void __launch_bounds__(THREADS, 1)
wd_fused_kernel(const float* __restrict__ user,      // [B,64]
                const float* __restrict__ price,     // [B,2]
                const float* __restrict__ temporal,  // [B,2]
                const float* __restrict__ item_emb,  // [1e6,64]
                const float* __restrict__ cat_emb,   // [1001,32]
                const float* __restrict__ wide1,     // [10000,1]
                const float* __restrict__ wide2,     // [10000,1]
                const float* __restrict__ crossW,    // [1e8]
                const int*   __restrict__ item_ids,  // [B]
                const int*   __restrict__ cat_ids,   // [B]
                const int*   __restrict__ wf1,       // [B]
                const int*   __restrict__ wf2,       // [B]
                const float* __restrict__ W1, const float* __restrict__ b1,
                const float* __restrict__ W2, const float* __restrict__ b2,
                const float* __restrict__ W3, const float* __restrict__ b3,
                const float* __restrict__ W4, const float* __restrict__ b4,
                const float* __restrict__ g1, const float* __restrict__ be1,
                const float* __restrict__ g2, const float* __restrict__ be2,
                const float* __restrict__ g3, const float* __restrict__ be3,
                float* __restrict__ out) {
    // ---- shared layout ----
    float* w1s = sm;                    // 164*128
    float* b1s = w1s + 164 * 128;       // 128
    float* w2s = b1s + 128;             // 128*64
    float* b2s = w2s + 128 * 64;        // 64
    float* w3s = b2s + 64;              // 64*32
    float* b3s = w3s + 64 * 32;         // 32
    float* w4s = b3s + 32;              // 32
    float* x_s = w4s + 32;              // 32*XS
    float* h1s = x_s + TILE * XS;       // 32*H1S
    float* h2s = h1s + TILE * H1S;      // 32*H2S
    float* h3s = h2s + TILE * H2S;      // 32*H3S
    int*   ids = (int*)(h3s + TILE * H3S);  // item[32] cat[32] f1[32] f2[32]

    const int tid  = threadIdx.x;
    const int lane = tid & 31;
    const int wg   = tid >> 5;
    const float inv = rsqrtf(1.0f + 1e-5f);  // BN eval: running var = 1

    // ---- load weights once, folding BN scale (g*inv) into W, bias into b ----
    for (int i = tid; i < 164 * 128; i += THREADS) {
        int j = i & 127;
        w1s[i] = W1[i] * (g1[j] * inv);
    }
    for (int i = tid; i < 128 * 64; i += THREADS) {
        int j = i & 63;
        w2s[i] = W2[i] * (g2[j] * inv);
    }
    for (int i = tid; i < 64 * 32; i += THREADS) {
        int j = i & 31;
        w3s[i] = W3[i] * (g3[j] * inv);
    }
    if (tid < 128) b1s[tid] = b1[tid] * (g1[tid] * inv) + be1[tid];
    if (tid < 64)  b2s[tid] = b2[tid] * (g2[tid] * inv) + be2[tid];
    if (tid < 32) {
        b3s[tid] = b3[tid] * (g3[tid] * inv) + be3[tid];
        w4s[tid] = W4[tid];
    }
    const float b4v = b4[0];

    for (int t = 0; t < TPC; ++t) {
        const int tile = blockIdx.x + t * GRID;
        const int base = tile * TILE;

        __syncthreads();  // weights ready / previous tile done with ids & x_s

        // ---- stage per-row ids ----
        if (tid < 32)       ids[tid]       = item_ids[base + tid];
        else if (tid < 64)  ids[tid]       = cat_ids[base + tid - 32];
        else if (tid < 96)  ids[tid]       = wf1[base + tid - 64];
        else if (tid < 128) ids[tid]       = wf2[base + tid - 96];
        __syncthreads();

        // ---- gather/concat x tile: [32][164] ----
        for (int idx = tid; idx < TILE * 164; idx += THREADS) {
            int r = idx / 164;
            int k = idx - r * 164;
            int row = base + r;
            float v;
            if (k < 64)       v = user[row * 64 + k];
            else if (k < 128) v = item_emb[(long long)ids[r] * 64 + (k - 64)];
            else if (k < 160) v = cat_emb[ids[32 + r] * 32 + (k - 128)];
            else if (k < 162) v = price[row * 2 + (k - 160)];
            else              v = temporal[row * 2 + (k - 162)];
            x_s[r * XS + k] = v;
        }
        __syncthreads();

        const unsigned long long z = pk2(0.0f, 0.0f);

        // ---- layer1: [32 x 164] @ [164 x 128]; thread = 4 rows (4*wg) x 4 cols (4*lane)
        {
            unsigned long long a0[4], a1[4];
#pragma unroll
            for (int r = 0; r < 4; ++r) { a0[r] = z; a1[r] = z; }
            const float* xr = x_s + (4 * wg) * XS;
            const float* wc = w1s + 4 * lane;
#pragma unroll 4
            for (int k = 0; k < 164; ++k) {
                float4 wv = *(const float4*)(wc + k * 128);
                unsigned long long w01 = pk2(wv.x, wv.y);
                unsigned long long w23 = pk2(wv.z, wv.w);
#pragma unroll
                for (int r = 0; r < 4; ++r) {
                    float xv = xr[r * XS + k];
                    unsigned long long xx = pk2(xv, xv);
                    ffma2(a0[r], xx, w01);
                    ffma2(a1[r], xx, w23);
                }
            }
            float bx = b1s[4 * lane], by = b1s[4 * lane + 1];
            float bz = b1s[4 * lane + 2], bw = b1s[4 * lane + 3];
#pragma unroll
            for (int r = 0; r < 4; ++r) {
                float v0, v1, v2, v3;
                upk2(a0[r], v0, v1);
                upk2(a1[r], v2, v3);
                float4 o;
                o.x = fmaxf(v0 + bx, 0.0f);
                o.y = fmaxf(v1 + by, 0.0f);
                o.z = fmaxf(v2 + bz, 0.0f);
                o.w = fmaxf(v3 + bw, 0.0f);
                *(float4*)(h1s + (4 * wg + r) * H1S + 4 * lane) = o;
            }
        }
        __syncthreads();

        // ---- layer2: [32 x 128] @ [128 x 64]; thread = 4 rows x 2 cols (2*lane)
        {
            unsigned long long a[4];
#pragma unroll
            for (int r = 0; r < 4; ++r) a[r] = z;
            const float* hr = h1s + (4 * wg) * H1S;
            const float* wc = w2s + 2 * lane;
#pragma unroll 4
            for (int k = 0; k < 128; ++k) {
                float2 wv = *(const float2*)(wc + k * 64);
                unsigned long long wp = pk2(wv.x, wv.y);
#pragma unroll
                for (int r = 0; r < 4; ++r) {
                    float h = hr[r * H1S + k];
                    ffma2(a[r], pk2(h, h), wp);
                }
            }
            float bx = b2s[2 * lane], by = b2s[2 * lane + 1];
#pragma unroll
            for (int r = 0; r < 4; ++r) {
                float v0, v1;
                upk2(a[r], v0, v1);
                float2 o;
                o.x = fmaxf(v0 + bx, 0.0f);
                o.y = fmaxf(v1 + by, 0.0f);
                *(float2*)(h2s + (4 * wg + r) * H2S + 2 * lane) = o;
            }
        }
        __syncthreads();

        // ---- layer3: [32 x 64] @ [64 x 32]; thread = 4 rows x 1 col (lane), rows packed
        {
            unsigned long long a01 = z, a23 = z;
            const float* hr = h2s + (4 * wg) * H2S;
#pragma unroll 4
            for (int k = 0; k < 64; ++k) {
                float w = w3s[k * 32 + lane];
                unsigned long long wp = pk2(w, w);
                ffma2(a01, pk2(hr[k], hr[H2S + k]), wp);
                ffma2(a23, pk2(hr[2 * H2S + k], hr[3 * H2S + k]), wp);
            }
            float bb = b3s[lane];
            float v0, v1, v2, v3;
            upk2(a01, v0, v1);
            upk2(a23, v2, v3);
            h3s[(4 * wg + 0) * H3S + lane] = fmaxf(v0 + bb, 0.0f);
            h3s[(4 * wg + 1) * H3S + lane] = fmaxf(v1 + bb, 0.0f);
            h3s[(4 * wg + 2) * H3S + lane] = fmaxf(v2 + bb, 0.0f);
            h3s[(4 * wg + 3) * H3S + lane] = fmaxf(v3 + bb, 0.0f);
        }
        __syncthreads();

        // ---- layer4 (32 -> 1) + wide component; one thread per row ----
        if (tid < 32) {
            const float* hr = h3s + tid * H3S;
            float d = b4v;
#pragma unroll
            for (int k = 0; k < 32; ++k) d = fmaf(hr[k], w4s[k], d);
            int f1 = ids[64 + tid];
            int f2 = ids[96 + tid];
            float w = wide1[f1] + wide2[f2] + crossW[(long long)f1 * 10000 + f2];
            out[base + tid] = d + w;
        }
    }
}

#define SMEM_FLOATS (164 * 128 + 128 + 128 * 64 + 64 + 64 * 32 + 32 + 32 + \
                     TILE * XS + TILE * H1S + TILE * H2S + TILE * H3S + 128)
#define SMEM_BYTES (SMEM_FLOATS * 4)

extern "C" void kernel_launch(void* const* d_in, const int* in_sizes, int n_in,
                              void* d_out, int out_size) {
    (void)in_sizes; (void)n_in; (void)out_size;
    static bool attr_set = false;
    if (!attr_set) {
        cudaFuncSetAttribute(wd_fused_kernel,
                             cudaFuncAttributeMaxDynamicSharedMemorySize, SMEM_BYTES);
        attr_set = true;
    }
    wd_fused_kernel<<<GRID, THREADS, SMEM_BYTES>>>(
        (const float*)d_in[0],   // user_embeddings
        (const float*)d_in[1],   // price_features
        (const float*)d_in[2],   // temporal_features
        (const float*)d_in[3],   // item_emb
        (const float*)d_in[4],   // cat_emb
        (const float*)d_in[5],   // wide_emb1
        (const float*)d_in[6],   // wide_emb2
        (const float*)d_in[7],   // cross_W
        (const int*)d_in[8],     // item_ids
        (const int*)d_in[9],     // category_ids
        (const int*)d_in[10],    // wf1
        (const int*)d_in[11],    // wf2
        (const float*)d_in[12], (const float*)d_in[13],   // W1, b1
        (const float*)d_in[14], (const float*)d_in[15],   // W2, b2
        (const float*)d_in[16], (const float*)d_in[17],   // W3, b3
        (const float*)d_in[18], (const float*)d_in[19],   // W4, b4
        (const float*)d_in[20], (const float*)d_in[21],   // g1, be1
        (const float*)d_in[22], (const float*)d_in[23],   // g2, be2
        (const float*)d_in[24], (const float*)d_in[25],   // g3, be3
        (float*)d_out);
}

// round 2
// speedup vs baseline: 1.2125x; 1.2125x over previous
#include <cuda_runtime.h>

// WideAndDeepModel fused kernel v2, sm_103a.
// 128 persistent CTAs x 512 threads (16 warps/SM). All weights (BN-folded) in
// SMEM. 64-row tiles. Activations stored TRANSPOSED + DUPLICATED in SMEM so the
// packed fma.rn.f32x2 inner loops need zero MOVs: weights via warp-uniform
// LDS128 broadcast, activations via conflict-free LDS64. One 85KB SMEM region
// is reused xT -> h1T -> h2T/h3 via deferred (register-held) stores.

#define TILE    64
#define THREADS 512
#define GRID    128
#define TPC     2          // 16384 / (64*128)

#define XTS  130           // xT dup: [164][130]
#define H1TS 128           // h1T dup: [128][128]
#define H2TS 128           // h2T dup: [64][128]
#define H3S  33            // h3: [64][33]

// SMEM float offsets
#define OFF_W1  0
#define OFF_B1  20992
#define OFF_W2  21120
#define OFF_B2  29312
#define OFF_W3  29376
#define OFF_B3  31424
#define OFF_W4  31456
#define OFF_R1  31488      // 21320 floats: xT(164*130) >= h1T(16384) >= h2T(8192)+h3(2112)
#define OFF_H3  (OFF_R1 + 8192)
#define OFF_IDS 52808      // 256 ints
#define SMEM_FLOATS 53064
#define SMEM_BYTES (SMEM_FLOATS * 4)

typedef unsigned long long ull;

__device__ __forceinline__ ull pk2(float a, float b) {
    ull r;
    asm("mov.b64 %0, {%1, %2};" : "=l"(r) : "f"(a), "f"(b));
    return r;
}
__device__ __forceinline__ void upk2(ull v, float& a, float& b) {
    asm("mov.b64 {%0, %1}, %2;" : "=f"(a), "=f"(b) : "l"(v));
}
__device__ __forceinline__ void ffma2(ull& d, ull a, ull b) {
    asm("fma.rn.f32x2 %0, %1, %2, %0;" : "+l"(d) : "l"(a), "l"(b));
}

extern __shared__ float sm[];

__global__ void __launch_bounds__(THREADS, 1)
wd_fused_v2(const float* __restrict__ user,      // [B,64]
            const float* __restrict__ price,     // [B,2]
            const float* __restrict__ temporal,  // [B,2]
            const float* __restrict__ item_emb,  // [1e6,64]
            const float* __restrict__ cat_emb,   // [1001,32]
            const float* __restrict__ wide1,     // [10000]
            const float* __restrict__ wide2,     // [10000]
            const float* __restrict__ crossW,    // [1e8]
            const int*   __restrict__ item_ids,
            const int*   __restrict__ cat_ids,
            const int*   __restrict__ wf1,
            const int*   __restrict__ wf2,
            const float* __restrict__ W1, const float* __restrict__ b1,
            const float* __restrict__ W2, const float* __restrict__ b2,
            const float* __restrict__ W3, const float* __restrict__ b3,
            const float* __restrict__ W4, const float* __restrict__ b4,
            const float* __restrict__ g1, const float* __restrict__ be1,
            const float* __restrict__ g2, const float* __restrict__ be2,
            const float* __restrict__ g3, const float* __restrict__ be3,
            float* __restrict__ out) {
    float* w1s = sm + OFF_W1;
    float* b1s = sm + OFF_B1;
    float* w2s = sm + OFF_W2;
    float* b2s = sm + OFF_B2;
    float* w3s = sm + OFF_W3;
    float* b3s = sm + OFF_B3;
    float* w4s = sm + OFF_W4;
    float* R1  = sm + OFF_R1;
    float* h3p = sm + OFF_H3;
    int*   idsm = (int*)(sm + OFF_IDS);

    const int tid  = threadIdx.x;
    const int lane = tid & 31;
    const int w    = tid >> 5;
    const float inv = rsqrtf(1.0f + 1e-5f);   // BN eval: running var = 1

    // ---- load weights once, fold BN (scale into W, bias into b) ----
    for (int i = tid; i < 164 * 128; i += THREADS) {
        int j = i & 127;
        w1s[i] = W1[i] * (g1[j] * inv);
    }
    for (int i = tid; i < 128 * 64; i += THREADS) {
        int j = i & 63;
        w2s[i] = W2[i] * (g2[j] * inv);
    }
    for (int i = tid; i < 64 * 32; i += THREADS) {
        int j = i & 31;
        w3s[i] = W3[i] * (g3[j] * inv);
    }
    if (tid < 128) b1s[tid] = b1[tid] * (g1[tid] * inv) + be1[tid];
    if (tid < 64)  b2s[tid] = b2[tid] * (g2[tid] * inv) + be2[tid];
    if (tid < 32) {
        b3s[tid] = b3[tid] * (g3[tid] * inv) + be3[tid];
        w4s[tid] = W4[tid];
    }
    const float b4v = b4[0];

    for (int t = 0; t < TPC; ++t) {
        const int base = (blockIdx.x + t * GRID) * TILE;

        __syncthreads();  // weights ready / prior tile fully consumed

        // ---- stage ids: item[0:64) cat[64:128) f1[128:192) f2[192:256) ----
        if (tid < 256) {
            int which = tid >> 6, r = tid & 63;
            const int* p = which == 0 ? item_ids : which == 1 ? cat_ids
                         : which == 2 ? wf1 : wf2;
            idsm[tid] = p[base + r];
        }
        __syncthreads();

        // ---- wide prefetch (latency hidden under gather + L1) ----
        float wv1 = 0.f, wv2 = 0.f, wcx = 0.f;
        if (tid < 64) {
            int f1 = idsm[128 + tid];
            int f2 = idsm[192 + tid];
            wv1 = wide1[f1];
            wv2 = wide2[f2];
            wcx = crossW[(long long)f1 * 10000 + f2];
        }

        // ---- gather into xT dup: xT[k][2r] = (x,x) ----
#pragma unroll
        for (int i = 0; i < 8; ++i) {             // user 64x64
            int idx = tid + i * 512;
            int r = idx >> 6, c = idx & 63;
            float v = user[(base + r) * 64 + c];
            *(ull*)(R1 + c * XTS + 2 * r) = pk2(v, v);
        }
#pragma unroll
        for (int i = 0; i < 8; ++i) {             // item 64x64 (gather)
            int idx = tid + i * 512;
            int r = idx >> 6, c = idx & 63;
            long long id = idsm[r];
            float v = item_emb[id * 64 + c];
            *(ull*)(R1 + (64 + c) * XTS + 2 * r) = pk2(v, v);
        }
#pragma unroll
        for (int i = 0; i < 4; ++i) {             // cat 64x32 (gather)
            int idx = tid + i * 512;
            int r = idx >> 5, c = idx & 31;
            int id = idsm[64 + r];
            float v = cat_emb[id * 32 + c];
            *(ull*)(R1 + (128 + c) * XTS + 2 * r) = pk2(v, v);
        }
        if (tid < 128) {                          // price / temporal 64x2 each
            int r = tid >> 1, c = tid & 1;
            float v = price[(base + r) * 2 + c];
            *(ull*)(R1 + (160 + c) * XTS + 2 * r) = pk2(v, v);
            float v2 = temporal[(base + r) * 2 + c];
            *(ull*)(R1 + (162 + c) * XTS + 2 * r) = pk2(v2, v2);
        }
        __syncthreads();

        // ---- L1: [64 x 164] @ [164 x 128] ----
        // warp -> cols [8w, 8w+8); thread -> rows {lane, lane+32}
        ull a[8];
#pragma unroll
        for (int i = 0; i < 8; ++i) a[i] = 0ull;
        {
            const float* wp_ = w1s + 8 * w;
            const float* xp  = R1 + 2 * lane;
#pragma unroll 4
            for (int k = 0; k < 164; ++k) {
                float4 wa = *(const float4*)(wp_ + k * 128);
                float4 wb = *(const float4*)(wp_ + k * 128 + 4);
                ull x0 = *(const ull*)(xp + k * XTS);
                ull x1 = *(const ull*)(xp + k * XTS + 64);
                ull w01 = pk2(wa.x, wa.y), w23 = pk2(wa.z, wa.w);
                ull w45 = pk2(wb.x, wb.y), w67 = pk2(wb.z, wb.w);
                ffma2(a[0], x0, w01); ffma2(a[1], x0, w23);
                ffma2(a[2], x0, w45); ffma2(a[3], x0, w67);
                ffma2(a[4], x1, w01); ffma2(a[5], x1, w23);
                ffma2(a[6], x1, w45); ffma2(a[7], x1, w67);
            }
        }
        __syncthreads();   // xT dead; safe to overwrite R1 with h1T

        // ---- store h1T dup (bias + relu) ----
        {
            float4 ba = *(const float4*)(b1s + 8 * w);
            float4 bb = *(const float4*)(b1s + 8 * w + 4);
            float bias[8] = {ba.x, ba.y, ba.z, ba.w, bb.x, bb.y, bb.z, bb.w};
#pragma unroll
            for (int h = 0; h < 2; ++h) {
                int rr = 2 * lane + 64 * h;
#pragma unroll
                for (int p = 0; p < 4; ++p) {
                    float v0, v1;
                    upk2(a[h * 4 + p], v0, v1);
                    v0 = fmaxf(v0 + bias[2 * p], 0.f);
                    v1 = fmaxf(v1 + bias[2 * p + 1], 0.f);
                    *(ull*)(R1 + (8 * w + 2 * p) * H1TS + rr) = pk2(v0, v0);
                    *(ull*)(R1 + (8 * w + 2 * p + 1) * H1TS + rr) = pk2(v1, v1);
                }
            }
        }
        __syncthreads();

        // ---- L2: [64 x 128] @ [128 x 64]; warp -> cols [4w,4w+4) ----
        ull c_[4];
#pragma unroll
        for (int i = 0; i < 4; ++i) c_[i] = 0ull;
        {
            const float* wp2 = w2s + 4 * w;
            const float* hp  = R1 + 2 * lane;
#pragma unroll 4
            for (int k = 0; k < 128; ++k) {
                float4 wv = *(const float4*)(wp2 + k * 64);
                ull w01 = pk2(wv.x, wv.y), w23 = pk2(wv.z, wv.w);
                ull h0 = *(const ull*)(hp + k * H1TS);
                ull h1 = *(const ull*)(hp + k * H1TS + 64);
                ffma2(c_[0], h0, w01); ffma2(c_[1], h0, w23);
                ffma2(c_[2], h1, w01); ffma2(c_[3], h1, w23);
            }
        }
        __syncthreads();   // h1T dead; safe to overwrite with h2T

        // ---- store h2T dup (bias + relu) ----
        {
            float4 bv = *(const float4*)(b2s + 4 * w);
            float bias2[4] = {bv.x, bv.y, bv.z, bv.w};
#pragma unroll
            for (int h = 0; h < 2; ++h) {
                int rr = 2 * lane + 64 * h;
#pragma unroll
                for (int p = 0; p < 2; ++p) {
                    float v0, v1;
                    upk2(c_[h * 2 + p], v0, v1);
                    v0 = fmaxf(v0 + bias2[2 * p], 0.f);
                    v1 = fmaxf(v1 + bias2[2 * p + 1], 0.f);
                    *(ull*)(R1 + (4 * w + 2 * p) * H2TS + rr) = pk2(v0, v0);
                    *(ull*)(R1 + (4 * w + 2 * p + 1) * H2TS + rr) = pk2(v1, v1);
                }
            }
        }
        __syncthreads();

        // ---- L3: [64 x 64] @ [64 x 32]; warp -> cols {2w, 2w+1} ----
        {
            ull d0 = 0ull, d1 = 0ull;
            const float* wp3 = w3s + 2 * w;
            const float* hp  = R1 + 2 * lane;
#pragma unroll 4
            for (int k = 0; k < 64; ++k) {
                float2 wv = *(const float2*)(wp3 + k * 32);
                ull wpk = pk2(wv.x, wv.y);
                ull h0 = *(const ull*)(hp + k * H2TS);
                ull h1 = *(const ull*)(hp + k * H2TS + 64);
                ffma2(d0, h0, wpk);
                ffma2(d1, h1, wpk);
            }
            // h3 region disjoint from live h2T -> store directly
            float bb0 = b3s[2 * w], bb1 = b3s[2 * w + 1];
            float v0, v1;
            upk2(d0, v0, v1);
            h3p[lane * H3S + 2 * w]     = fmaxf(v0 + bb0, 0.f);
            h3p[lane * H3S + 2 * w + 1] = fmaxf(v1 + bb1, 0.f);
            upk2(d1, v0, v1);
            h3p[(lane + 32) * H3S + 2 * w]     = fmaxf(v0 + bb0, 0.f);
            h3p[(lane + 32) * H3S + 2 * w + 1] = fmaxf(v1 + bb1, 0.f);
        }
        __syncthreads();

        // ---- L4 (32 -> 1) + wide; one thread per row ----
        if (tid < 64) {
            const float* hr = h3p + tid * H3S;
            float s0 = 0.f, s1 = 0.f, s2 = 0.f, s3 = 0.f;
#pragma unroll
            for (int k = 0; k < 32; k += 4) {
                s0 = fmaf(hr[k],     w4s[k],     s0);
                s1 = fmaf(hr[k + 1], w4s[k + 1], s1);
                s2 = fmaf(hr[k + 2], w4s[k + 2], s2);
                s3 = fmaf(hr[k + 3], w4s[k + 3], s3);
            }
            out[base + tid] = (s0 + s1) + (s2 + s3) + b4v + wv1 + wv2 + wcx;
        }
    }
}

extern "C" void kernel_launch(void* const* d_in, const int* in_sizes, int n_in,
                              void* d_out, int out_size) {
    (void)in_sizes; (void)n_in; (void)out_size;
    static bool attr_set = false;
    if (!attr_set) {
        cudaFuncSetAttribute(wd_fused_v2,
                             cudaFuncAttributeMaxDynamicSharedMemorySize, SMEM_BYTES);
        attr_set = true;
    }
    wd_fused_v2<<<GRID, THREADS, SMEM_BYTES>>>(
        (const float*)d_in[0],   // user_embeddings
        (const float*)d_in[1],   // price_features
        (const float*)d_in[2],   // temporal_features
        (const float*)d_in[3],   // item_emb
        (const float*)d_in[4],   // cat_emb
        (const float*)d_in[5],   // wide_emb1
        (const float*)d_in[6],   // wide_emb2
        (const float*)d_in[7],   // cross_W
        (const int*)d_in[8],     // item_ids
        (const int*)d_in[9],     // category_ids
        (const int*)d_in[10],    // wf1
        (const int*)d_in[11],    // wf2
        (const float*)d_in[12], (const float*)d_in[13],   // W1, b1
        (const float*)d_in[14], (const float*)d_in[15],   // W2, b2
        (const float*)d_in[16], (const float*)d_in[17],   // W3, b3
        (const float*)d_in[18], (const float*)d_in[19],   // W4, b4
        (const float*)d_in[20], (const float*)d_in[21],   // g1, be1
        (const float*)d_in[22], (const float*)d_in[23],   // g2, be2
        (const float*)d_in[24], (const float*)d_in[25],   // g3, be3
        (float*)d_out);
}